// round 2
// baseline (speedup 1.0000x reference)
#include <cuda_runtime.h>

#define BB 2
#define SS 4096
#define HH 512
#define NH 8
#define HD 64
#define MROWS (BB * SS)          // 8192
#define QKV_COLS (3 * HH)        // 1536
#define LOGD (-0.10536051565782628f)

// Scratch (device globals: no allocation allowed in kernel_launch)
__device__ float g_qkv[MROWS * QKV_COLS];   // [b*S+s][3H]  (q|k|v interleaved per row)
__device__ float g_attn[MROWS * HH];        // [b*S+s][H]   attention output (bqhd flattened)

// ---------------------------------------------------------------------------
// GEMM: C[m][n] = sum_k A[m][k] * W[n][k]  (+ bias[n] if bias != nullptr)
// A row-major [M,K], W row-major [N,K]. Tiles 64x64, BK=16, 256 thr, 4x4/thr.
// ---------------------------------------------------------------------------
__global__ __launch_bounds__(256) void gemm_awt(
    const float* __restrict__ A, const float* __restrict__ W,
    const float* __restrict__ bias, float* __restrict__ C,
    int Mdim, int Ndim, int Kdim)
{
    __shared__ float As[16][68];   // [k][m] transposed
    __shared__ float Bs[16][68];   // [k][n] transposed

    const int tid = threadIdx.x;
    const int tx = tid & 15;       // n-tile coord
    const int ty = tid >> 4;       // m-tile coord
    const int m0 = blockIdx.y * 64;
    const int n0 = blockIdx.x * 64;

    const int lrow = tid >> 2;     // 0..63
    const int lkq  = tid & 3;      // 0..3 (which float4 of the 16-wide k chunk)

    const float* Arow = A + (size_t)(m0 + lrow) * Kdim + lkq * 4;
    const float* Wrow = W + (size_t)(n0 + lrow) * Kdim + lkq * 4;

    float acc[4][4];
#pragma unroll
    for (int i = 0; i < 4; i++)
#pragma unroll
        for (int j = 0; j < 4; j++) acc[i][j] = 0.f;

    for (int kk = 0; kk < Kdim; kk += 16) {
        float4 av = *(const float4*)(Arow + kk);
        float4 wv = *(const float4*)(Wrow + kk);
        __syncthreads();           // previous iteration finished reading smem
        As[lkq * 4 + 0][lrow] = av.x;
        As[lkq * 4 + 1][lrow] = av.y;
        As[lkq * 4 + 2][lrow] = av.z;
        As[lkq * 4 + 3][lrow] = av.w;
        Bs[lkq * 4 + 0][lrow] = wv.x;
        Bs[lkq * 4 + 1][lrow] = wv.y;
        Bs[lkq * 4 + 2][lrow] = wv.z;
        Bs[lkq * 4 + 3][lrow] = wv.w;
        __syncthreads();
#pragma unroll
        for (int k = 0; k < 16; k++) {
            float4 a4 = *(const float4*)&As[k][ty * 4];
            float4 b4 = *(const float4*)&Bs[k][tx * 4];
            float a[4] = {a4.x, a4.y, a4.z, a4.w};
            float b[4] = {b4.x, b4.y, b4.z, b4.w};
#pragma unroll
            for (int i = 0; i < 4; i++)
#pragma unroll
                for (int j = 0; j < 4; j++) acc[i][j] += a[i] * b[j];
        }
    }

    float bv[4] = {0.f, 0.f, 0.f, 0.f};
    if (bias != nullptr) {
#pragma unroll
        for (int j = 0; j < 4; j++) bv[j] = bias[n0 + tx * 4 + j];
    }
#pragma unroll
    for (int i = 0; i < 4; i++) {
        float4 r;
        r.x = acc[i][0] + bv[0];
        r.y = acc[i][1] + bv[1];
        r.z = acc[i][2] + bv[2];
        r.w = acc[i][3] + bv[3];
        *(float4*)(C + (size_t)(m0 + ty * 4 + i) * Ndim + n0 + tx * 4) = r;
    }
}

// ---------------------------------------------------------------------------
// Flash-style attention, fp32. 64-query tile per block, 64-key tiles.
// grid: (S/64, B*NH), block 256 (16x16).
// ---------------------------------------------------------------------------

// swizzled index into a d-major [64][64] tile: column rotated by 4*((d>>2)&15)
__device__ __forceinline__ int tidx(int d, int c) {
    return d * 64 + ((c + (((d >> 2) & 15) << 2)) & 63);
}

__global__ __launch_bounds__(256, 3) void attn_kernel(
    const float* __restrict__ qkv, float* __restrict__ out)
{
    extern __shared__ float sm[];
    float* smQ = sm;               // [d][q] swizzled, prescaled by 1/8
    float* smK = sm + 64 * 64;     // [d][kk] swizzled
    float* smV = sm + 2 * 64 * 64; // [kk][d] natural
    float* smP = sm + 3 * 64 * 64; // [q][kk] natural

    const int tid = threadIdx.x;
    const int tx = tid & 15;
    const int ty = tid >> 4;
    const int tx4 = tx * 4, ty4 = ty * 4;

    const int q0 = blockIdx.x * 64;
    const int bh = blockIdx.y;
    const int b = bh / NH, h = bh % NH;

    const float* qbase = qkv + (size_t)b * SS * QKV_COLS + h * HD;
    const float* kbase = qbase + HH;
    const float* vbase = qbase + 2 * HH;

    // Load Q tile (transposed, swizzled, prescaled)
#pragma unroll
    for (int j = 0; j < 4; j++) {
        int fi = tid + j * 256;          // 0..1023 over 64 rows x 16 float4
        int row = fi >> 4;
        int c4 = (fi & 15) << 2;
        float4 v = *(const float4*)(qbase + (size_t)(q0 + row) * QKV_COLS + c4);
        smQ[tidx(c4 + 0, row)] = v.x * 0.125f;
        smQ[tidx(c4 + 1, row)] = v.y * 0.125f;
        smQ[tidx(c4 + 2, row)] = v.z * 0.125f;
        smQ[tidx(c4 + 3, row)] = v.w * 0.125f;
    }

    float o[4][4];
#pragma unroll
    for (int i = 0; i < 4; i++)
#pragma unroll
        for (int j = 0; j < 4; j++) o[i][j] = 0.f;
    float mrow[4], lrow[4];
#pragma unroll
    for (int i = 0; i < 4; i++) { mrow[i] = -1e30f; lrow[i] = 0.f; }

    for (int kt = 0; kt < SS; kt += 64) {
        // Load K (transposed+swizzled) and V (natural) tiles
#pragma unroll
        for (int j = 0; j < 4; j++) {
            int fi = tid + j * 256;
            int row = fi >> 4;
            int c4 = (fi & 15) << 2;
            float4 kv = *(const float4*)(kbase + (size_t)(kt + row) * QKV_COLS + c4);
            smK[tidx(c4 + 0, row)] = kv.x;
            smK[tidx(c4 + 1, row)] = kv.y;
            smK[tidx(c4 + 2, row)] = kv.z;
            smK[tidx(c4 + 3, row)] = kv.w;
            float4 vv = *(const float4*)(vbase + (size_t)(kt + row) * QKV_COLS + c4);
            *(float4*)&smV[row * 64 + c4] = vv;
        }
        __syncthreads();

        // S = Q K^T (scale folded into Q)
        float s[4][4];
#pragma unroll
        for (int i = 0; i < 4; i++)
#pragma unroll
            for (int j = 0; j < 4; j++) s[i][j] = 0.f;
#pragma unroll 16
        for (int d = 0; d < 64; d++) {
            float4 a4 = *(const float4*)&smQ[tidx(d, ty4)];
            float4 b4 = *(const float4*)&smK[tidx(d, tx4)];
            float a[4] = {a4.x, a4.y, a4.z, a4.w};
            float bb[4] = {b4.x, b4.y, b4.z, b4.w};
#pragma unroll
            for (int i = 0; i < 4; i++)
#pragma unroll
                for (int j = 0; j < 4; j++) s[i][j] += a[i] * bb[j];
        }

        // bias + online softmax (row groups of 16 lanes along tx)
#pragma unroll
        for (int i = 0; i < 4; i++) {
            int qg = q0 + ty4 + i;
#pragma unroll
            for (int j = 0; j < 4; j++) {
                int kg = kt + tx4 + j;
                if (kg <= qg) s[i][j] += (float)(kg - qg) * LOGD;
            }
            float mx = fmaxf(fmaxf(s[i][0], s[i][1]), fmaxf(s[i][2], s[i][3]));
            mx = fmaxf(mx, __shfl_xor_sync(0xffffffffu, mx, 8, 16));
            mx = fmaxf(mx, __shfl_xor_sync(0xffffffffu, mx, 4, 16));
            mx = fmaxf(mx, __shfl_xor_sync(0xffffffffu, mx, 2, 16));
            mx = fmaxf(mx, __shfl_xor_sync(0xffffffffu, mx, 1, 16));
            float mn = fmaxf(mrow[i], mx);
            float corr = __expf(mrow[i] - mn);
            mrow[i] = mn;
            float rs = 0.f;
#pragma unroll
            for (int j = 0; j < 4; j++) { s[i][j] = __expf(s[i][j] - mn); rs += s[i][j]; }
            rs += __shfl_xor_sync(0xffffffffu, rs, 8, 16);
            rs += __shfl_xor_sync(0xffffffffu, rs, 4, 16);
            rs += __shfl_xor_sync(0xffffffffu, rs, 2, 16);
            rs += __shfl_xor_sync(0xffffffffu, rs, 1, 16);
            lrow[i] = lrow[i] * corr + rs;
#pragma unroll
            for (int j = 0; j < 4; j++) o[i][j] *= corr;
            *(float4*)&smP[(ty4 + i) * 64 + tx4] =
                make_float4(s[i][0], s[i][1], s[i][2], s[i][3]);
        }
        __syncthreads();

        // O += P V
#pragma unroll 16
        for (int kk = 0; kk < 64; kk++) {
            float a0 = smP[(ty4 + 0) * 64 + kk];
            float a1 = smP[(ty4 + 1) * 64 + kk];
            float a2 = smP[(ty4 + 2) * 64 + kk];
            float a3 = smP[(ty4 + 3) * 64 + kk];
            float4 b4 = *(const float4*)&smV[kk * 64 + tx4];
            o[0][0] += a0 * b4.x; o[0][1] += a0 * b4.y; o[0][2] += a0 * b4.z; o[0][3] += a0 * b4.w;
            o[1][0] += a1 * b4.x; o[1][1] += a1 * b4.y; o[1][2] += a1 * b4.z; o[1][3] += a1 * b4.w;
            o[2][0] += a2 * b4.x; o[2][1] += a2 * b4.y; o[2][2] += a2 * b4.z; o[2][3] += a2 * b4.w;
            o[3][0] += a3 * b4.x; o[3][1] += a3 * b4.y; o[3][2] += a3 * b4.z; o[3][3] += a3 * b4.w;
        }
        __syncthreads();   // before next tile overwrites smK/smV
    }

    // Normalize + write [b][q][h*64+d]
#pragma unroll
    for (int i = 0; i < 4; i++) {
        float inv = 1.0f / lrow[i];
        float4 r = make_float4(o[i][0] * inv, o[i][1] * inv, o[i][2] * inv, o[i][3] * inv);
        *(float4*)(out + (size_t)(b * SS + q0 + ty4 + i) * HH + h * HD + tx4) = r;
    }
}

// ---------------------------------------------------------------------------
extern "C" void kernel_launch(void* const* d_in, const int* in_sizes, int n_in,
                              void* d_out, int out_size)
{
    (void)in_sizes; (void)n_in; (void)out_size;
    const float* x     = (const float*)d_in[0];
    const float* wqkv  = (const float*)d_in[1];
    const float* wout  = (const float*)d_in[2];
    const float* bout  = (const float*)d_in[3];
    float* out = (float*)d_out;

    void* qkv_ptr = nullptr;
    void* attn_ptr = nullptr;
    cudaGetSymbolAddress(&qkv_ptr, g_qkv);
    cudaGetSymbolAddress(&attn_ptr, g_attn);

    const int SMEM_ATTN = 4 * 64 * 64 * (int)sizeof(float);  // 64 KB
    cudaFuncSetAttribute(attn_kernel, cudaFuncAttributeMaxDynamicSharedMemorySize, SMEM_ATTN);

    dim3 blk(256);
    // 1) qkv = x @ w_qkv^T : M=8192, N=1536, K=512
    gemm_awt<<<dim3(QKV_COLS / 64, MROWS / 64), blk>>>(
        x, wqkv, nullptr, (float*)qkv_ptr, MROWS, QKV_COLS, HH);
    // 2) attention
    attn_kernel<<<dim3(SS / 64, BB * NH), blk, SMEM_ATTN>>>(
        (const float*)qkv_ptr, (float*)attn_ptr);
    // 3) out = attn @ w_out^T + b_out : M=8192, N=512, K=512
    gemm_awt<<<dim3(HH / 64, MROWS / 64), blk>>>(
        (const float*)attn_ptr, wout, bout, out, MROWS, HH, HH);
}

// round 3
// speedup vs baseline: 3.3478x; 3.3478x over previous
#include <cuda_runtime.h>
#include <cstdint>

#define BB 2
#define SS 4096
#define HH 512
#define NH 8
#define HD 64
#define MROWS (BB * SS)          // 8192
#define QKV_COLS (3 * HH)        // 1536
#define LOGD (-0.10536051565782628f)

// Scratch (device globals: no allocation allowed in kernel_launch)
__device__ float g_qkv[MROWS * QKV_COLS];   // [b*S+s][3H]
__device__ float g_attn[MROWS * HH];        // [b*S+s][H]

// ---------------------------------------------------------------------------
// helpers
// ---------------------------------------------------------------------------
__device__ __forceinline__ uint32_t f2tf(float x) {
    uint32_t r;
    asm("cvt.rna.tf32.f32 %0, %1;" : "=r"(r) : "f"(x));
    return r;
}

// D += A * B  (m16n8k8, tf32 inputs, f32 accumulate)
__device__ __forceinline__ void mma8(float* d, const uint32_t* a, const uint32_t* b) {
    asm volatile(
        "mma.sync.aligned.m16n8k8.row.col.f32.tf32.tf32.f32 "
        "{%0,%1,%2,%3}, {%4,%5,%6,%7}, {%8,%9}, {%0,%1,%2,%3};\n"
        : "+f"(d[0]), "+f"(d[1]), "+f"(d[2]), "+f"(d[3])
        : "r"(a[0]), "r"(a[1]), "r"(a[2]), "r"(a[3]), "r"(b[0]), "r"(b[1]));
}

// ---------------------------------------------------------------------------
// TF32 tensor-core GEMM: C[m][n] = sum_k A[m][k] * W[n][k] (+ bias[n])
// CTA tile 128x64, 4 warps (each 32m x 64n), K chunks of 32.
// ---------------------------------------------------------------------------
#define ASTR 36
#define WSTR 36

__global__ __launch_bounds__(128, 2) void gemm_tc(
    const float* __restrict__ A, const float* __restrict__ W,
    const float* __restrict__ bias, float* __restrict__ C,
    int Ndim, int Kdim)
{
    __shared__ uint32_t sA[128 * ASTR];
    __shared__ uint32_t sW[64 * WSTR];

    const int tid = threadIdx.x;
    const int w = tid >> 5, lane = tid & 31;
    const int g = lane >> 2, tg = lane & 3;
    const int m0 = blockIdx.y * 128;
    const int n0 = blockIdx.x * 64;

    float acc[2][8][4] = {};

    for (int kk = 0; kk < Kdim; kk += 32) {
        float4 av[8], wv[4];
#pragma unroll
        for (int it = 0; it < 8; it++) {
            int fi = it * 128 + tid;
            int r = fi >> 3, c = (fi & 7) << 2;
            av[it] = *(const float4*)(A + (size_t)(m0 + r) * Kdim + kk + c);
        }
#pragma unroll
        for (int it = 0; it < 4; it++) {
            int fi = it * 128 + tid;
            int r = fi >> 3, c = (fi & 7) << 2;
            wv[it] = *(const float4*)(W + (size_t)(n0 + r) * Kdim + kk + c);
        }
        __syncthreads();
#pragma unroll
        for (int it = 0; it < 8; it++) {
            int fi = it * 128 + tid;
            int r = fi >> 3, c = (fi & 7) << 2;
            uint32_t* p = &sA[r * ASTR + c];
            p[0] = f2tf(av[it].x); p[1] = f2tf(av[it].y);
            p[2] = f2tf(av[it].z); p[3] = f2tf(av[it].w);
        }
#pragma unroll
        for (int it = 0; it < 4; it++) {
            int fi = it * 128 + tid;
            int r = fi >> 3, c = (fi & 7) << 2;
            uint32_t* p = &sW[r * WSTR + c];
            p[0] = f2tf(wv[it].x); p[1] = f2tf(wv[it].y);
            p[2] = f2tf(wv[it].z); p[3] = f2tf(wv[it].w);
        }
        __syncthreads();
#pragma unroll
        for (int ks = 0; ks < 4; ks++) {
            uint32_t afr[2][4];
#pragma unroll
            for (int mi = 0; mi < 2; mi++) {
                int row = w * 32 + mi * 16;
                afr[mi][0] = sA[(row + g) * ASTR + ks * 8 + tg];
                afr[mi][1] = sA[(row + g + 8) * ASTR + ks * 8 + tg];
                afr[mi][2] = sA[(row + g) * ASTR + ks * 8 + tg + 4];
                afr[mi][3] = sA[(row + g + 8) * ASTR + ks * 8 + tg + 4];
            }
#pragma unroll
            for (int ni = 0; ni < 8; ni++) {
                uint32_t bfr[2];
                bfr[0] = sW[(ni * 8 + g) * WSTR + ks * 8 + tg];
                bfr[1] = sW[(ni * 8 + g) * WSTR + ks * 8 + tg + 4];
                mma8(acc[0][ni], afr[0], bfr);
                mma8(acc[1][ni], afr[1], bfr);
            }
        }
        __syncthreads();
    }

    float bv0[8], bv1[8];
#pragma unroll
    for (int ni = 0; ni < 8; ni++) {
        int c = n0 + ni * 8 + tg * 2;
        bv0[ni] = bias ? bias[c] : 0.f;
        bv1[ni] = bias ? bias[c + 1] : 0.f;
    }
#pragma unroll
    for (int mi = 0; mi < 2; mi++)
#pragma unroll
        for (int ni = 0; ni < 8; ni++) {
            int row = m0 + w * 32 + mi * 16 + g;
            int col = n0 + ni * 8 + tg * 2;
            *(float2*)(C + (size_t)row * Ndim + col) =
                make_float2(acc[mi][ni][0] + bv0[ni], acc[mi][ni][1] + bv1[ni]);
            *(float2*)(C + (size_t)(row + 8) * Ndim + col) =
                make_float2(acc[mi][ni][2] + bv0[ni], acc[mi][ni][3] + bv1[ni]);
        }
}

// ---------------------------------------------------------------------------
// TF32 flash attention. CTA: 128 q-rows, 4 warps (32q x 64key each).
// grid: (S/128, B*NH), block 128.
// ---------------------------------------------------------------------------
#define QSTR 68
#define KSTR 68
#define VSTR 72
#define PSTR 68
#define ATTN_SMEM ((128 * QSTR + 64 * KSTR + 64 * VSTR + 128 * PSTR) * 4)

__global__ __launch_bounds__(128, 2) void attn_tc(
    const float* __restrict__ qkv, float* __restrict__ out)
{
    extern __shared__ uint32_t sm[];
    uint32_t* sQ = sm;                        // [128][68] tf32, prescaled
    uint32_t* sK = sQ + 128 * QSTR;           // [64][68]
    uint32_t* sV = sK + 64 * KSTR;            // [64][72]
    uint32_t* sP = sV + 64 * VSTR;            // [128][68]

    const int tid = threadIdx.x;
    const int w = tid >> 5, lane = tid & 31;
    const int g = lane >> 2, tg = lane & 3;
    const int q0 = blockIdx.x * 128;
    const int bh = blockIdx.y;
    const int b = bh >> 3, h = bh & 7;

    const float* qbase = qkv + (size_t)b * SS * QKV_COLS + h * HD;
    const float* kbase = qbase + HH;
    const float* vbase = qbase + 2 * HH;

    // Load Q tile (tf32, prescaled by 1/8)
#pragma unroll
    for (int it = 0; it < 16; it++) {
        int fi = it * 128 + tid;
        int r = fi >> 4, c = (fi & 15) << 2;
        float4 v = *(const float4*)(qbase + (size_t)(q0 + r) * QKV_COLS + c);
        uint32_t* p = &sQ[r * QSTR + c];
        p[0] = f2tf(v.x * 0.125f); p[1] = f2tf(v.y * 0.125f);
        p[2] = f2tf(v.z * 0.125f); p[3] = f2tf(v.w * 0.125f);
    }

    float oc[2][8][4] = {};
    float mrow[4] = {-1e30f, -1e30f, -1e30f, -1e30f};
    float lrow[4] = {0.f, 0.f, 0.f, 0.f};

    for (int kt = 0; kt < SS; kt += 64) {
        // Load K, V tiles (tf32)
#pragma unroll
        for (int it = 0; it < 8; it++) {
            int fi = it * 128 + tid;
            int r = fi >> 4, c = (fi & 15) << 2;
            float4 kv = *(const float4*)(kbase + (size_t)(kt + r) * QKV_COLS + c);
            float4 vv = *(const float4*)(vbase + (size_t)(kt + r) * QKV_COLS + c);
            uint32_t* pk = &sK[r * KSTR + c];
            pk[0] = f2tf(kv.x); pk[1] = f2tf(kv.y); pk[2] = f2tf(kv.z); pk[3] = f2tf(kv.w);
            uint32_t* pv = &sV[r * VSTR + c];
            pv[0] = f2tf(vv.x); pv[1] = f2tf(vv.y); pv[2] = f2tf(vv.z); pv[3] = f2tf(vv.w);
        }
        __syncthreads();

        // S = Q K^T  (scale folded into Q)
        float sc[2][8][4] = {};
#pragma unroll
        for (int ks = 0; ks < 8; ks++) {
            uint32_t afr[2][4];
#pragma unroll
            for (int mi = 0; mi < 2; mi++) {
                int row = w * 32 + mi * 16;
                afr[mi][0] = sQ[(row + g) * QSTR + ks * 8 + tg];
                afr[mi][1] = sQ[(row + g + 8) * QSTR + ks * 8 + tg];
                afr[mi][2] = sQ[(row + g) * QSTR + ks * 8 + tg + 4];
                afr[mi][3] = sQ[(row + g + 8) * QSTR + ks * 8 + tg + 4];
            }
#pragma unroll
            for (int ni = 0; ni < 8; ni++) {
                uint32_t bfr[2];
                bfr[0] = sK[(ni * 8 + g) * KSTR + ks * 8 + tg];
                bfr[1] = sK[(ni * 8 + g) * KSTR + ks * 8 + tg + 4];
                mma8(sc[0][ni], afr[0], bfr);
                mma8(sc[1][ni], afr[1], bfr);
            }
        }

        // Online softmax on C fragments. 4 row-states per thread:
        // rs = mi*2 + hi, global row = q0 + w*32 + mi*16 + hi*8 + g
#pragma unroll
        for (int mi = 0; mi < 2; mi++) {
#pragma unroll
            for (int hi = 0; hi < 2; hi++) {
                int rs = mi * 2 + hi;
                int qg = q0 + w * 32 + mi * 16 + hi * 8 + g;
                float ev[8][2];
                float vmax = -1e30f;
#pragma unroll
                for (int ni = 0; ni < 8; ni++) {
#pragma unroll
                    for (int cc = 0; cc < 2; cc++) {
                        int kg = kt + ni * 8 + tg * 2 + cc;
                        float sv = sc[mi][ni][hi * 2 + cc];
                        if (kg <= qg) sv += (float)(kg - qg) * LOGD;
                        ev[ni][cc] = sv;
                        vmax = fmaxf(vmax, sv);
                    }
                }
                vmax = fmaxf(vmax, __shfl_xor_sync(0xffffffffu, vmax, 1));
                vmax = fmaxf(vmax, __shfl_xor_sync(0xffffffffu, vmax, 2));
                float mn = fmaxf(mrow[rs], vmax);
                float corr = __expf(mrow[rs] - mn);
                mrow[rs] = mn;
                float rsum = 0.f;
#pragma unroll
                for (int ni = 0; ni < 8; ni++) {
#pragma unroll
                    for (int cc = 0; cc < 2; cc++) {
                        float e = __expf(ev[ni][cc] - mn);
                        ev[ni][cc] = e;
                        rsum += e;
                    }
                }
                rsum += __shfl_xor_sync(0xffffffffu, rsum, 1);
                rsum += __shfl_xor_sync(0xffffffffu, rsum, 2);
                lrow[rs] = lrow[rs] * corr + rsum;
                int prow = w * 32 + mi * 16 + hi * 8 + g;
#pragma unroll
                for (int ni = 0; ni < 8; ni++) {
                    oc[mi][ni][hi * 2 + 0] *= corr;
                    oc[mi][ni][hi * 2 + 1] *= corr;
                    uint32_t* pp = &sP[prow * PSTR + ni * 8 + tg * 2];
                    pp[0] = f2tf(ev[ni][0]);
                    pp[1] = f2tf(ev[ni][1]);
                }
            }
        }
        __syncwarp();   // P rows are warp-private: warp-level visibility suffices

        // O += P V  (k over 64 keys, n over 64 d)
#pragma unroll
        for (int ks = 0; ks < 8; ks++) {
            uint32_t afr[2][4];
#pragma unroll
            for (int mi = 0; mi < 2; mi++) {
                int row = w * 32 + mi * 16;
                afr[mi][0] = sP[(row + g) * PSTR + ks * 8 + tg];
                afr[mi][1] = sP[(row + g + 8) * PSTR + ks * 8 + tg];
                afr[mi][2] = sP[(row + g) * PSTR + ks * 8 + tg + 4];
                afr[mi][3] = sP[(row + g + 8) * PSTR + ks * 8 + tg + 4];
            }
#pragma unroll
            for (int ni = 0; ni < 8; ni++) {
                uint32_t bfr[2];
                bfr[0] = sV[(ks * 8 + tg) * VSTR + ni * 8 + g];
                bfr[1] = sV[(ks * 8 + tg + 4) * VSTR + ni * 8 + g];
                mma8(oc[0][ni], afr[0], bfr);
                mma8(oc[1][ni], afr[1], bfr);
            }
        }
        __syncthreads();   // before next tile overwrites sK/sV
    }

    // Normalize + write [b][q][h*64+d]
    float inv[4];
#pragma unroll
    for (int rs = 0; rs < 4; rs++) inv[rs] = 1.0f / lrow[rs];
#pragma unroll
    for (int mi = 0; mi < 2; mi++)
#pragma unroll
        for (int ni = 0; ni < 8; ni++) {
            int row = q0 + w * 32 + mi * 16 + g;
            int col = h * HD + ni * 8 + tg * 2;
            *(float2*)(out + (size_t)(b * SS + row) * HH + col) =
                make_float2(oc[mi][ni][0] * inv[mi * 2 + 0],
                            oc[mi][ni][1] * inv[mi * 2 + 0]);
            *(float2*)(out + (size_t)(b * SS + row + 8) * HH + col) =
                make_float2(oc[mi][ni][2] * inv[mi * 2 + 1],
                            oc[mi][ni][3] * inv[mi * 2 + 1]);
        }
}

// ---------------------------------------------------------------------------
extern "C" void kernel_launch(void* const* d_in, const int* in_sizes, int n_in,
                              void* d_out, int out_size)
{
    (void)in_sizes; (void)n_in; (void)out_size;
    const float* x    = (const float*)d_in[0];
    const float* wqkv = (const float*)d_in[1];
    const float* wout = (const float*)d_in[2];
    const float* bout = (const float*)d_in[3];
    float* out = (float*)d_out;

    void* qkv_ptr = nullptr;
    void* attn_ptr = nullptr;
    cudaGetSymbolAddress(&qkv_ptr, g_qkv);
    cudaGetSymbolAddress(&attn_ptr, g_attn);

    cudaFuncSetAttribute(attn_tc, cudaFuncAttributeMaxDynamicSharedMemorySize, ATTN_SMEM);

    dim3 blk(128);
    // 1) qkv = x @ w_qkv^T : M=8192, N=1536, K=512
    gemm_tc<<<dim3(QKV_COLS / 64, MROWS / 128), blk>>>(
        x, wqkv, nullptr, (float*)qkv_ptr, QKV_COLS, HH);
    // 2) attention
    attn_tc<<<dim3(SS / 128, BB * NH), blk, ATTN_SMEM>>>(
        (const float*)qkv_ptr, (float*)attn_ptr);
    // 3) out = attn @ w_out^T + b_out : M=8192, N=512, K=512
    gemm_tc<<<dim3(HH / 64, MROWS / 128), blk>>>(
        (const float*)attn_ptr, wout, bout, out, HH, HH);
}

// round 5
// speedup vs baseline: 3.5125x; 1.0492x over previous
#include <cuda_runtime.h>
#include <cstdint>

#define BB 2
#define SS 4096
#define HH 512
#define NH 8
#define HD 64
#define MROWS (BB * SS)
#define QKV_COLS (3 * HH)
#define LOG2D (-0.15200309344504997f)
#define QSCALE 0.18033688011112042f

__device__ float g_qkv[MROWS * QKV_COLS];
__device__ float g_vT[BB * NH * HD * SS];
__device__ float g_attn[MROWS * HH];

__device__ __forceinline__ uint32_t f2tf(float x) {
    uint32_t r;
    asm("cvt.rna.tf32.f32 %0, %1;" : "=r"(r) : "f"(x));
    return r;
}
__device__ __forceinline__ float ex2(float x) {
    float r;
    asm("ex2.approx.ftz.f32 %0, %1;" : "=f"(r) : "f"(x));
    return r;
}
__device__ __forceinline__ void mma8(float* d, const uint32_t* a, const uint32_t* b) {
    asm volatile(
        "mma.sync.aligned.m16n8k8.row.col.f32.tf32.tf32.f32 "
        "{%0,%1,%2,%3}, {%4,%5,%6,%7}, {%8,%9}, {%0,%1,%2,%3};\n"
        : "+f"(d[0]), "+f"(d[1]), "+f"(d[2]), "+f"(d[3])
        : "r"(a[0]), "r"(a[1]), "r"(a[2]), "r"(a[3]), "r"(b[0]), "r"(b[1]));
}
__device__ __forceinline__ void ldsm4(uint32_t* r, uint32_t saddr) {
    asm volatile("ldmatrix.sync.aligned.m8n8.x4.shared.b16 {%0,%1,%2,%3}, [%4];"
                 : "=r"(r[0]), "=r"(r[1]), "=r"(r[2]), "=r"(r[3]) : "r"(saddr));
}
__device__ __forceinline__ void cpa16(uint32_t dst, const void* src) {
    asm volatile("cp.async.cg.shared.global [%0], [%1], 16;" :: "r"(dst), "l"(src));
}
#define CP_COMMIT() asm volatile("cp.async.commit_group;" ::: "memory")
#define CP_WAIT0()  asm volatile("cp.async.wait_group 0;" ::: "memory")

// ---------------------------------------------------------------------------
// TF32 GEMM with ldmatrix fragments. CTA 128x64, 4 warps, K chunks of 32.
// mode 0: plain fp32 (+bias). mode 1: qkv epilogue (scale/round/V-scatter).
// ---------------------------------------------------------------------------
#define GSTR 36

__global__ __launch_bounds__(128, 2) void gemm_tc(
    const float* __restrict__ A, const float* __restrict__ W,
    const float* __restrict__ bias, float* __restrict__ C,
    float* __restrict__ vT, int Ndim, int Kdim, int mode)
{
    __shared__ uint32_t sA[128 * GSTR];
    __shared__ uint32_t sW[64 * GSTR];

    const int tid = threadIdx.x;
    const int w = tid >> 5, lane = tid & 31;
    const int g = lane >> 2, tg = lane & 3;
    const int mat = lane >> 3, mr = lane & 7;
    const int m0 = blockIdx.y * 128;
    const int n0 = blockIdx.x * 64;

    const uint32_t sAu = (uint32_t)__cvta_generic_to_shared(sA);
    const uint32_t sWu = (uint32_t)__cvta_generic_to_shared(sW);
    const uint32_t a_off = ((((mat & 1) << 3) + mr) * GSTR + ((mat >> 1) << 2)) << 2;
    const uint32_t b_off = ((((mat >> 1) << 3) + mr) * GSTR + ((mat & 1) << 2)) << 2;

    float acc[2][8][4] = {};

    for (int kk = 0; kk < Kdim; kk += 32) {
        float4 av[8], wv[4];
#pragma unroll
        for (int it = 0; it < 8; it++) {
            int fi = it * 128 + tid;
            int r = fi >> 3, c = (fi & 7) << 2;
            av[it] = *(const float4*)(A + (size_t)(m0 + r) * Kdim + kk + c);
        }
#pragma unroll
        for (int it = 0; it < 4; it++) {
            int fi = it * 128 + tid;
            int r = fi >> 3, c = (fi & 7) << 2;
            wv[it] = *(const float4*)(W + (size_t)(n0 + r) * Kdim + kk + c);
        }
        __syncthreads();
#pragma unroll
        for (int it = 0; it < 8; it++) {
            int fi = it * 128 + tid;
            int r = fi >> 3, c = (fi & 7) << 2;
            uint32_t* p = &sA[r * GSTR + c];
            p[0] = f2tf(av[it].x); p[1] = f2tf(av[it].y);
            p[2] = f2tf(av[it].z); p[3] = f2tf(av[it].w);
        }
#pragma unroll
        for (int it = 0; it < 4; it++) {
            int fi = it * 128 + tid;
            int r = fi >> 3, c = (fi & 7) << 2;
            uint32_t* p = &sW[r * GSTR + c];
            p[0] = f2tf(wv[it].x); p[1] = f2tf(wv[it].y);
            p[2] = f2tf(wv[it].z); p[3] = f2tf(wv[it].w);
        }
        __syncthreads();
#pragma unroll
        for (int ks = 0; ks < 4; ks++) {
            uint32_t afr[2][4];
            ldsm4(afr[0], sAu + (w * 32) * (GSTR * 4) + a_off + ks * 32);
            ldsm4(afr[1], sAu + (w * 32 + 16) * (GSTR * 4) + a_off + ks * 32);
#pragma unroll
            for (int p = 0; p < 4; p++) {
                uint32_t bfr[4];
                ldsm4(bfr, sWu + p * 16 * (GSTR * 4) + b_off + ks * 32);
                mma8(acc[0][2 * p + 0], afr[0], bfr);
                mma8(acc[0][2 * p + 1], afr[0], bfr + 2);
                mma8(acc[1][2 * p + 0], afr[1], bfr);
                mma8(acc[1][2 * p + 1], afr[1], bfr + 2);
            }
        }
        __syncthreads();
    }

#pragma unroll
    for (int mi = 0; mi < 2; mi++)
#pragma unroll
        for (int ni = 0; ni < 8; ni++) {
            float* a = acc[mi][ni];
            int row = m0 + w * 32 + mi * 16 + g;
            int col = n0 + ni * 8 + tg * 2;
            if (mode == 0) {
                float b0 = bias ? bias[col] : 0.f;
                float b1 = bias ? bias[col + 1] : 0.f;
                *(float2*)(C + (size_t)row * Ndim + col) = make_float2(a[0] + b0, a[1] + b1);
                *(float2*)(C + (size_t)(row + 8) * Ndim + col) = make_float2(a[2] + b0, a[3] + b1);
            } else {
                int region = n0 >> 9;
                if (region < 2) {
                    float scl = (region == 0) ? QSCALE : 1.f;
                    *(float2*)(C + (size_t)row * Ndim + col) =
                        make_float2(__uint_as_float(f2tf(a[0] * scl)),
                                    __uint_as_float(f2tf(a[1] * scl)));
                    *(float2*)(C + (size_t)(row + 8) * Ndim + col) =
                        make_float2(__uint_as_float(f2tf(a[2] * scl)),
                                    __uint_as_float(f2tf(a[3] * scl)));
                } else {
                    int b = row >> 12, s = row & 4095;
                    int hv = (col - 1024) >> 6, d = (col - 1024) & 63;
                    float* vb = vT + (size_t)((b * NH + hv) * HD) * SS;
                    vb[(size_t)d * SS + s]           = __uint_as_float(f2tf(a[0]));
                    vb[(size_t)(d + 1) * SS + s]     = __uint_as_float(f2tf(a[1]));
                    vb[(size_t)d * SS + s + 8]       = __uint_as_float(f2tf(a[2]));
                    vb[(size_t)(d + 1) * SS + s + 8] = __uint_as_float(f2tf(a[3]));
                }
            }
        }
}

// ---------------------------------------------------------------------------
// TF32 flash attention: 256 threads / 8 warps, 128 q per CTA, 16 q per warp.
// Q/K pre-rounded tf32 (Q pre-scaled by 0.125*log2e), V pre-transposed [d][s].
// ---------------------------------------------------------------------------
#define TSTR 68
#define ATTN_SMEM (384 * TSTR * 4)

__global__ __launch_bounds__(256, 2) void attn_tc(
    const float* __restrict__ qkv, const float* __restrict__ vT,
    float* __restrict__ out)
{
    extern __shared__ uint32_t sm[];
    uint32_t* sQ = sm;
    uint32_t* sK = sQ + 128 * TSTR;
    uint32_t* sV = sK + 64 * TSTR;
    uint32_t* sP = sV + 64 * TSTR;

    const int tid = threadIdx.x;
    const int w = tid >> 5, lane = tid & 31;
    const int g = lane >> 2, tg = lane & 3;
    const int mat = lane >> 3, mr = lane & 7;
    const int q0 = blockIdx.x * 128;
    const int bh = blockIdx.y;
    const int b = bh >> 3, h = bh & 7;

    const float* qbase = qkv + (size_t)b * SS * QKV_COLS + h * HD;
    const float* kbase = qbase + HH;
    const float* vtb = vT + (size_t)bh * HD * SS;

    const uint32_t sQu = (uint32_t)__cvta_generic_to_shared(sQ);
    const uint32_t sKu = (uint32_t)__cvta_generic_to_shared(sK);
    const uint32_t sVu = (uint32_t)__cvta_generic_to_shared(sV);
    const uint32_t sPu = (uint32_t)__cvta_generic_to_shared(sP);

    const uint32_t a_off = ((((mat & 1) << 3) + mr) * TSTR + ((mat >> 1) << 2)) << 2;
    const uint32_t b_off = ((((mat >> 1) << 3) + mr) * TSTR + ((mat & 1) << 2)) << 2;
    const uint32_t qa = sQu + w * (16 * TSTR * 4) + a_off;
    const uint32_t pa = sPu + w * (16 * TSTR * 4) + a_off;

    // ---- full tile loaders: 64-float rows = 16 x 16B chunks per row ----
    // Q: 128 rows * 16 chunks = 2048 chunks -> 8 per thread (256 thr)
    {
#pragma unroll
        for (int it = 0; it < 8; it++) {
            int fi = it * 256 + tid;
            int r = fi >> 4, c = (fi & 15) << 2;
            cpa16(sQu + (r * TSTR + c) * 4, qbase + (size_t)(q0 + r) * QKV_COLS + c);
        }
        // K, V tile 0: 64 rows * 16 chunks = 1024 chunks -> 4 per thread each
#pragma unroll
        for (int it = 0; it < 4; it++) {
            int fi = it * 256 + tid;
            int r = fi >> 4, c = (fi & 15) << 2;
            cpa16(sKu + (r * TSTR + c) * 4, kbase + (size_t)r * QKV_COLS + c);
            cpa16(sVu + (r * TSTR + c) * 4, vtb + (size_t)r * SS + c);
        }
        CP_COMMIT();
    }

    float oc[8][4] = {};
    float mrow[2] = {-1e30f, -1e30f};
    float lrow[2] = {0.f, 0.f};

    for (int kt = 0; kt < SS; kt += 64) {
        CP_WAIT0();
        __syncthreads();

        // S = Q K^T
        float sc[8][4] = {};
#pragma unroll
        for (int ks = 0; ks < 8; ks++) {
            uint32_t afr[4];
            ldsm4(afr, qa + ks * 32);
#pragma unroll
            for (int p = 0; p < 4; p++) {
                uint32_t bfr[4];
                ldsm4(bfr, sKu + b_off + p * (16 * TSTR * 4) + ks * 32);
                mma8(sc[2 * p + 0], afr, bfr);
                mma8(sc[2 * p + 1], afr, bfr + 2);
            }
        }

        // online softmax (log2 domain)
#pragma unroll
        for (int hi = 0; hi < 2; hi++) {
            int qg = q0 + w * 16 + hi * 8 + g;
            float ev[8][2];
            float vmax = -1e30f;
#pragma unroll
            for (int ni = 0; ni < 8; ni++) {
#pragma unroll
                for (int cc = 0; cc < 2; cc++) {
                    int kg = kt + ni * 8 + tg * 2 + cc;
                    float sv = sc[ni][hi * 2 + cc];
                    if (kg <= qg) sv += (float)(kg - qg) * LOG2D;
                    ev[ni][cc] = sv;
                    vmax = fmaxf(vmax, sv);
                }
            }
            vmax = fmaxf(vmax, __shfl_xor_sync(0xffffffffu, vmax, 1));
            vmax = fmaxf(vmax, __shfl_xor_sync(0xffffffffu, vmax, 2));
            float mn = fmaxf(mrow[hi], vmax);
            float corr = ex2(mrow[hi] - mn);
            mrow[hi] = mn;
            float rsum = 0.f;
#pragma unroll
            for (int ni = 0; ni < 8; ni++) {
#pragma unroll
                for (int cc = 0; cc < 2; cc++) {
                    float e = ex2(ev[ni][cc] - mn);
                    ev[ni][cc] = e;
                    rsum += e;
                }
            }
            rsum += __shfl_xor_sync(0xffffffffu, rsum, 1);
            rsum += __shfl_xor_sync(0xffffffffu, rsum, 2);
            lrow[hi] = lrow[hi] * corr + rsum;
            int prow = w * 16 + hi * 8 + g;
#pragma unroll
            for (int ni = 0; ni < 8; ni++) {
                oc[ni][hi * 2 + 0] *= corr;
                oc[ni][hi * 2 + 1] *= corr;
                uint32_t e0 = f2tf(ev[ni][0]);
                uint32_t e1 = f2tf(ev[ni][1]);
                uint32_t addr = sPu + (prow * TSTR + ni * 8 + tg * 2) * 4;
                asm volatile("st.shared.v2.u32 [%0], {%1,%2};" :: "r"(addr), "r"(e0), "r"(e1));
            }
        }
        __syncwarp();

        // O += P V
#pragma unroll
        for (int ks = 0; ks < 8; ks++) {
            uint32_t pfr[4];
            ldsm4(pfr, pa + ks * 32);
#pragma unroll
            for (int p = 0; p < 4; p++) {
                uint32_t vfr[4];
                ldsm4(vfr, sVu + b_off + p * (16 * TSTR * 4) + ks * 32);
                mma8(oc[2 * p + 0], pfr, vfr);
                mma8(oc[2 * p + 1], pfr, vfr + 2);
            }
        }
        __syncthreads();

        if (kt + 64 < SS) {
#pragma unroll
            for (int it = 0; it < 4; it++) {
                int fi = it * 256 + tid;
                int r = fi >> 4, c = (fi & 15) << 2;
                cpa16(sKu + (r * TSTR + c) * 4,
                      kbase + (size_t)(kt + 64 + r) * QKV_COLS + c);
                cpa16(sVu + (r * TSTR + c) * 4,
                      vtb + (size_t)r * SS + kt + 64 + c);
            }
            CP_COMMIT();
        }
    }

    float inv0 = 1.0f / lrow[0], inv1 = 1.0f / lrow[1];
#pragma unroll
    for (int ni = 0; ni < 8; ni++) {
        int row = q0 + w * 16 + g;
        int col = h * HD + ni * 8 + tg * 2;
        *(float2*)(out + (size_t)(b * SS + row) * HH + col) =
            make_float2(oc[ni][0] * inv0, oc[ni][1] * inv0);
        *(float2*)(out + (size_t)(b * SS + row + 8) * HH + col) =
            make_float2(oc[ni][2] * inv1, oc[ni][3] * inv1);
    }
}

// ---------------------------------------------------------------------------
extern "C" void kernel_launch(void* const* d_in, const int* in_sizes, int n_in,
                              void* d_out, int out_size)
{
    (void)in_sizes; (void)n_in; (void)out_size;
    const float* x    = (const float*)d_in[0];
    const float* wqkv = (const float*)d_in[1];
    const float* wout = (const float*)d_in[2];
    const float* bout = (const float*)d_in[3];
    float* out = (float*)d_out;

    void *qkv_ptr = nullptr, *vT_ptr = nullptr, *attn_ptr = nullptr;
    cudaGetSymbolAddress(&qkv_ptr, g_qkv);
    cudaGetSymbolAddress(&vT_ptr, g_vT);
    cudaGetSymbolAddress(&attn_ptr, g_attn);

    cudaFuncSetAttribute(attn_tc, cudaFuncAttributeMaxDynamicSharedMemorySize, ATTN_SMEM);

    gemm_tc<<<dim3(QKV_COLS / 64, MROWS / 128), 128>>>(
        x, wqkv, nullptr, (float*)qkv_ptr, (float*)vT_ptr, QKV_COLS, HH, 1);
    attn_tc<<<dim3(SS / 128, BB * NH), 256, ATTN_SMEM>>>(
        (const float*)qkv_ptr, (const float*)vT_ptr, (float*)attn_ptr);
    gemm_tc<<<dim3(HH / 64, MROWS / 128), 128>>>(
        (const float*)attn_ptr, wout, bout, out, nullptr, HH, HH, 0);
}